// round 4
// baseline (speedup 1.0000x reference)
#include <cuda_runtime.h>
#include <cstdint>
#include <cstddef>

// Problem constants
#define BB 4
#define LL 4096
#define DD 1024
#define HH 16
#define HDIM 64
#define KSEL 1024
#define ATT_SCALE 0.125f   // 1/sqrt(64)

typedef unsigned long long u64;
typedef ulonglong2 u64x2;

// ---- packed f32x2 helpers (sm_100+ PTX) -----------------------------------
__device__ __forceinline__ u64 pack2(float lo, float hi) {
    u64 r; asm("mov.b64 %0, {%1, %2};" : "=l"(r) : "f"(lo), "f"(hi)); return r;
}
__device__ __forceinline__ float2 unpack2(u64 v) {
    float2 r; asm("mov.b64 {%0, %1}, %2;" : "=f"(r.x), "=f"(r.y) : "l"(v)); return r;
}
__device__ __forceinline__ void fma2(u64& d, u64 a, u64 b) {
    asm("fma.rn.f32x2 %0, %1, %2, %0;" : "+l"(d) : "l"(a), "l"(b));
}
__device__ __forceinline__ void mul2(u64& d, u64 a) {
    asm("mul.rn.f32x2 %0, %0, %1;" : "+l"(d) : "l"(a));
}

// ---------------------------------------------------------------------------
// Device scratch (static __device__ arrays: allocation-free per harness rules)
// ---------------------------------------------------------------------------
__device__ float g_scores[BB * LL];
__device__ int   g_idx[BB * KSEL];
__device__ float g_qb[(size_t)BB * KSEL * DD];
__device__ float g_kb[(size_t)BB * KSEL * DD];
__device__ float g_vb[(size_t)BB * KSEL * DD];
__device__ float g_ob[(size_t)BB * KSEL * DD];

// ---------------------------------------------------------------------------
// 1) Router: scores[b][l] = dot(x[b,l,:], w_router)   (bias is rank-invariant)
// ---------------------------------------------------------------------------
__global__ void __launch_bounds__(256) router_kernel(const float* __restrict__ x,
                                                     const float* __restrict__ w)
{
    int warp = (blockIdx.x * blockDim.x + threadIdx.x) >> 5;
    int lane = threadIdx.x & 31;
    if (warp >= BB * LL) return;
    const float4* xr = (const float4*)(x + (size_t)warp * DD);
    const float4* wr = (const float4*)w;
    float s = 0.f;
#pragma unroll
    for (int i = lane; i < DD / 4; i += 32) {
        float4 a = xr[i], b = wr[i];
        s += a.x * b.x + a.y * b.y + a.z * b.z + a.w * b.w;
    }
#pragma unroll
    for (int o = 16; o; o >>= 1) s += __shfl_xor_sync(0xffffffffu, s, o);
    if (lane == 0) g_scores[warp] = s;
}

// ---------------------------------------------------------------------------
// 2) Top-K via full bitonic sort of 4096 (score desc, index asc) per batch.
// ---------------------------------------------------------------------------
__global__ void __launch_bounds__(1024) topk_kernel()
{
    __shared__ unsigned long long key[LL];
    const int b = blockIdx.x;
    const int tid = threadIdx.x;

    for (int i = tid; i < LL; i += 1024) {
        unsigned u = __float_as_uint(g_scores[b * LL + i]);
        u = (u & 0x80000000u) ? ~u : (u | 0x80000000u); // monotone map (ascending)
        unsigned inv = ~u;                              // descending score
        key[i] = ((unsigned long long)inv << 32) | (unsigned)i;
    }
    __syncthreads();

    for (int k = 2; k <= LL; k <<= 1) {
        for (int j = k >> 1; j > 0; j >>= 1) {
            for (int t = tid; t < LL; t += 1024) {
                int ixj = t ^ j;
                if (ixj > t) {
                    unsigned long long a = key[t], c = key[ixj];
                    bool up = ((t & k) == 0);
                    if ((a > c) == up) { key[t] = c; key[ixj] = a; }
                }
            }
            __syncthreads();
        }
    }
    if (tid < KSEL)
        g_idx[b * KSEL + tid] = (int)(key[tid] & 0xFFFFFFFFu);
}

// ---------------------------------------------------------------------------
// 128x128x16 fp32 GEMM tile with packed f32x2 inner loop (256 thr, 8x8 micro).
// acc2[i][jp] holds column pairs (2jp, 2jp+1). B pairs come straight from Bs
// row-major via 128-bit loads; A values broadcast-duplicated once per row.
// ---------------------------------------------------------------------------
__device__ __forceinline__ void gemm_128x128(const float* __restrict__ A,
                                             const int*   __restrict__ a_rows,
                                             const float* __restrict__ W,
                                             float*       __restrict__ C,
                                             const int*   __restrict__ c_rows)
{
    __shared__ float As[16][128];
    __shared__ float Bs[16][128];

    const int m0 = blockIdx.y * 128;
    const int n0 = blockIdx.x * 128;
    const int tid = threadIdx.x;

    const int lrow = tid >> 1;          // 0..127 (A row within tile)
    const int lk   = (tid & 1) << 3;    // 0 or 8
    int arow_idx = m0 + lrow;
    if (a_rows) arow_idx = a_rows[arow_idx];
    const float* arow = A + (size_t)arow_idx * DD;

    const int bkr = tid >> 5;           // 0..7
    const int bnc = (tid & 31) << 2;    // 0..124 step 4

    const int ty = tid >> 4;            // 0..15 -> rows ty*8..+7
    const int tx = tid & 15;            // 0..15 -> cols tx*8..+7

    u64 acc2[8][4];
#pragma unroll
    for (int i = 0; i < 8; i++)
#pragma unroll
        for (int jp = 0; jp < 4; jp++) acc2[i][jp] = 0ull;

    for (int k0 = 0; k0 < DD; k0 += 16) {
        float4 a0 = *(const float4*)(arow + k0 + lk);
        float4 a1 = *(const float4*)(arow + k0 + lk + 4);
        float4 b0 = *(const float4*)(W + (size_t)(k0 + bkr) * DD + n0 + bnc);
        float4 b1 = *(const float4*)(W + (size_t)(k0 + bkr + 8) * DD + n0 + bnc);

        As[lk + 0][lrow] = a0.x; As[lk + 1][lrow] = a0.y;
        As[lk + 2][lrow] = a0.z; As[lk + 3][lrow] = a0.w;
        As[lk + 4][lrow] = a1.x; As[lk + 5][lrow] = a1.y;
        As[lk + 6][lrow] = a1.z; As[lk + 7][lrow] = a1.w;
        *(float4*)&Bs[bkr][bnc]     = b0;
        *(float4*)&Bs[bkr + 8][bnc] = b1;
        __syncthreads();

#pragma unroll
        for (int kk = 0; kk < 16; kk++) {
            float4 af0 = *(const float4*)&As[kk][ty * 8];
            float4 af1 = *(const float4*)&As[kk][ty * 8 + 4];
            u64x2 bq0 = *(const u64x2*)&Bs[kk][tx * 8];
            u64x2 bq1 = *(const u64x2*)&Bs[kk][tx * 8 + 4];
            u64 bp[4] = {bq0.x, bq0.y, bq1.x, bq1.y};
            float av[8] = {af0.x, af0.y, af0.z, af0.w, af1.x, af1.y, af1.z, af1.w};
#pragma unroll
            for (int i = 0; i < 8; i++) {
                u64 ad = pack2(av[i], av[i]);
#pragma unroll
                for (int jp = 0; jp < 4; jp++)
                    fma2(acc2[i][jp], ad, bp[jp]);
            }
        }
        __syncthreads();
    }

#pragma unroll
    for (int i = 0; i < 8; i++) {
        int r = m0 + ty * 8 + i;
        int crow_idx = c_rows ? c_rows[r] : r;
        float* cp = C + (size_t)crow_idx * DD + n0 + tx * 8;
        u64x2 lo; lo.x = acc2[i][0]; lo.y = acc2[i][1];
        u64x2 hi; hi.x = acc2[i][2]; hi.y = acc2[i][3];
        *(u64x2*)cp       = lo;   // (c0,c1,c2,c3)
        *(u64x2*)(cp + 4) = hi;   // (c4,c5,c6,c7)
    }
}

// 3) QKV projections: grid.z in [0,12): b = z/3, w = z%3. A rows gathered by idx.
__global__ void __launch_bounds__(256, 2) qkv_kernel(const float* __restrict__ x,
                                                     const float* __restrict__ wq,
                                                     const float* __restrict__ wk,
                                                     const float* __restrict__ wv)
{
    const int z = blockIdx.z;
    const int b = z / 3, w = z % 3;
    const float* W = (w == 0) ? wq : (w == 1) ? wk : wv;
    float* C = ((w == 0) ? g_qb : (w == 1) ? g_kb : g_vb) + (size_t)b * KSEL * DD;
    gemm_128x128(x + (size_t)b * LL * DD, g_idx + b * KSEL, W, C, nullptr);
}

// 5) O projection + scatter into out[b, idx[r], :]
__global__ void __launch_bounds__(256, 2) oproj_kernel(const float* __restrict__ wo,
                                                       float* __restrict__ out)
{
    const int b = blockIdx.z;
    gemm_128x128(g_ob + (size_t)b * KSEL * DD, nullptr, wo,
                 out + (size_t)b * LL * DD, g_idx + b * KSEL);
}

// ---------------------------------------------------------------------------
// 4) Flash-style causal attention, 64x64 tiles, packed-f32x2 math.
//    Qt2/Kt2: pair-interleaved over d  -> [dp][r*2 + (d&1)]  (S-loop contraction)
//    Vs2:     pair-interleaved over j  -> [jp][c*2 + (j&1)]  (PV-loop contraction)
//    Ps:      [r][68] scalar probabilities (j-pairs adjacent per row)
// ---------------------------------------------------------------------------
#define ATT_SMEM_FLOATS (4096 * 3 + 64 * 68)
#define ATT_SMEM_BYTES  (ATT_SMEM_FLOATS * 4)

__global__ void __launch_bounds__(256) attn_kernel()
{
    extern __shared__ float sm[];
    float* Qt2 = sm;           // [32][128]  d-pair interleaved
    float* Kt2 = sm + 4096;    // [32][128]  d-pair interleaved
    float* Vs2 = sm + 8192;    // [32][128]  j-pair interleaved
    float* Ps  = sm + 12288;   // [64][68]   padded

    const int qt  = (int)gridDim.x - 1 - (int)blockIdx.x; // long blocks first
    const int h   = blockIdx.y;
    const int b   = blockIdx.z;
    const int tid = threadIdx.x;
    const int ty  = tid >> 4;   // 0..15 -> rows ty*4..+3
    const int tx  = tid & 15;   // 0..15 -> cols tx*4..+3
    const int q0  = qt * 64;

    const float* qbase = g_qb + (size_t)b * KSEL * DD + h * HDIM;
    const float* kbase = g_kb + (size_t)b * KSEL * DD + h * HDIM;
    const float* vbase = g_vb + (size_t)b * KSEL * DD + h * HDIM;
    float*       obase = g_ob + (size_t)b * KSEL * DD + h * HDIM;

    // Load Q tile: pair-interleave over d, pre-scale
    {
        const int r  = tid >> 2;
        const int dc = (tid & 3) << 4;
        const float* src = qbase + (size_t)(q0 + r) * DD + dc;
#pragma unroll
        for (int qd = 0; qd < 4; qd++) {
            float4 v = *(const float4*)(src + qd * 4);
            int dp = (dc + qd * 4) >> 1;               // d even
            *(u64*)&Qt2[(dp + 0) * 128 + r * 2] = pack2(v.x * ATT_SCALE, v.y * ATT_SCALE);
            *(u64*)&Qt2[(dp + 1) * 128 + r * 2] = pack2(v.z * ATT_SCALE, v.w * ATT_SCALE);
        }
    }

    float mrow[4], lrow[4];
    u64 o2[4][4];                 // [row][col], halves = even/odd j partials
#pragma unroll
    for (int i = 0; i < 4; i++) {
        mrow[i] = -1e30f; lrow[i] = 0.f;
#pragma unroll
        for (int c = 0; c < 4; c++) o2[i][c] = 0ull;
    }

    for (int kt = 0; kt <= qt; kt++) {
        __syncthreads(); // prior PV reads done before reloading Kt2/Vs2
        {
            const int r  = tid >> 2;
            const int dc = (tid & 3) << 4;
            const float* ks = kbase + (size_t)(kt * 64 + r) * DD + dc;
            const float* vs = vbase + (size_t)(kt * 64 + r) * DD + dc;
            const int jp  = r >> 1;
            const int jlo = r & 1;
            float* vd = &Vs2[jp * 128 + jlo];
#pragma unroll
            for (int qd = 0; qd < 4; qd++) {
                int d = dc + qd * 4;
                float4 kv = *(const float4*)(ks + qd * 4);
                int dp = d >> 1;
                *(u64*)&Kt2[(dp + 0) * 128 + r * 2] = pack2(kv.x, kv.y);
                *(u64*)&Kt2[(dp + 1) * 128 + r * 2] = pack2(kv.z, kv.w);
                float4 vv = *(const float4*)(vs + qd * 4);
                vd[(d + 0) * 2] = vv.x;
                vd[(d + 1) * 2] = vv.y;
                vd[(d + 2) * 2] = vv.z;
                vd[(d + 3) * 2] = vv.w;
            }
        }
        __syncthreads();

        // S = Q K^T : f32x2 partial sums over even/odd d
        u64 s2[4][4];
#pragma unroll
        for (int i = 0; i < 4; i++)
#pragma unroll
            for (int j = 0; j < 4; j++) s2[i][j] = 0ull;

#pragma unroll 8
        for (int dp = 0; dp < 32; dp++) {
            const float* qrow = &Qt2[dp * 128 + ty * 8];
            const float* krow = &Kt2[dp * 128 + tx * 8];
            u64x2 qa = *(const u64x2*)qrow;
            u64x2 qb = *(const u64x2*)(qrow + 4);
            u64x2 ka = *(const u64x2*)krow;
            u64x2 kb = *(const u64x2*)(krow + 4);
            u64 q2[4] = {qa.x, qa.y, qb.x, qb.y};
            u64 k2[4] = {ka.x, ka.y, kb.x, kb.y};
#pragma unroll
            for (int i = 0; i < 4; i++)
#pragma unroll
                for (int j = 0; j < 4; j++)
                    fma2(s2[i][j], q2[i], k2[j]);
        }

        // Horizontal-add halves -> scalar S
        float s[4][4];
#pragma unroll
        for (int i = 0; i < 4; i++)
#pragma unroll
            for (int j = 0; j < 4; j++) {
                float2 p = unpack2(s2[i][j]);
                s[i][j] = p.x + p.y;
            }

        // Causal mask on diagonal tile
        if (kt == qt) {
#pragma unroll
            for (int i = 0; i < 4; i++)
#pragma unroll
                for (int j = 0; j < 4; j++)
                    if (tx * 4 + j > ty * 4 + i) s[i][j] = -1e30f;
        }

        // Online softmax (row reductions within 16-lane tx groups)
#pragma unroll
        for (int i = 0; i < 4; i++) {
            float mx = fmaxf(fmaxf(s[i][0], s[i][1]), fmaxf(s[i][2], s[i][3]));
#pragma unroll
            for (int off = 8; off; off >>= 1)
                mx = fmaxf(mx, __shfl_xor_sync(0xffffffffu, mx, off));
            float mnew  = fmaxf(mrow[i], mx);
            float alpha = __expf(mrow[i] - mnew);
            mrow[i] = mnew;
            float ps = 0.f;
#pragma unroll
            for (int j = 0; j < 4; j++) {
                float p = __expf(s[i][j] - mnew);
                s[i][j] = p; ps += p;
            }
#pragma unroll
            for (int off = 8; off; off >>= 1)
                ps += __shfl_xor_sync(0xffffffffu, ps, off);
            lrow[i] = lrow[i] * alpha + ps;
            u64 a2 = pack2(alpha, alpha);
#pragma unroll
            for (int c = 0; c < 4; c++) mul2(o2[i][c], a2);
            *(float4*)&Ps[(ty * 4 + i) * 68 + tx * 4] =
                make_float4(s[i][0], s[i][1], s[i][2], s[i][3]);
        }
        __syncthreads();

        // O += P @ V : f32x2 partial sums over even/odd j
#pragma unroll 8
        for (int jp = 0; jp < 32; jp++) {
            const float* vrow = &Vs2[jp * 128 + tx * 8];
            u64x2 va = *(const u64x2*)vrow;
            u64x2 vb = *(const u64x2*)(vrow + 4);
            u64 v2[4] = {va.x, va.y, vb.x, vb.y};
#pragma unroll
            for (int i = 0; i < 4; i++) {
                u64 p2 = *(const u64*)&Ps[(ty * 4 + i) * 68 + jp * 2];
#pragma unroll
                for (int c = 0; c < 4; c++)
                    fma2(o2[i][c], p2, v2[c]);
            }
        }
    }

#pragma unroll
    for (int i = 0; i < 4; i++) {
        float inv = 1.f / lrow[i];
        float* op = obase + (size_t)(q0 + ty * 4 + i) * DD + tx * 4;
        float2 c0 = unpack2(o2[i][0]);
        float2 c1 = unpack2(o2[i][1]);
        float2 c2 = unpack2(o2[i][2]);
        float2 c3 = unpack2(o2[i][3]);
        *(float4*)op = make_float4((c0.x + c0.y) * inv, (c1.x + c1.y) * inv,
                                   (c2.x + c2.y) * inv, (c3.x + c3.y) * inv);
    }
}

// ---------------------------------------------------------------------------
// Launch: copy-through + router -> topk -> QKV -> attention -> Oproj+scatter
// ---------------------------------------------------------------------------
extern "C" void kernel_launch(void* const* d_in, const int* in_sizes, int n_in,
                              void* d_out, int out_size)
{
    const float* x  = (const float*)d_in[0];
    const float* wr = (const float*)d_in[1];
    // d_in[2] = b_router: constant bias, rank-invariant, unused
    const float* wq = (const float*)d_in[3];
    const float* wk = (const float*)d_in[4];
    const float* wv = (const float*)d_in[5];
    const float* wo = (const float*)d_in[6];
    float* out = (float*)d_out;

    // Passthrough for unselected tokens (selected rows overwritten by oproj)
    cudaMemcpyAsync(out, x, (size_t)BB * LL * DD * sizeof(float),
                    cudaMemcpyDeviceToDevice);

    router_kernel<<<(BB * LL) / 8, 256>>>(x, wr);
    topk_kernel<<<BB, 1024>>>();
    qkv_kernel<<<dim3(8, 8, 12), 256>>>(x, wq, wk, wv);

    cudaFuncSetAttribute(attn_kernel,
                         cudaFuncAttributeMaxDynamicSharedMemorySize,
                         ATT_SMEM_BYTES);
    attn_kernel<<<dim3(16, HH, BB), 256, ATT_SMEM_BYTES>>>();

    oproj_kernel<<<dim3(8, 8, 4), 256>>>(wo, out);
}

// round 7
// speedup vs baseline: 1.0834x; 1.0834x over previous
#include <cuda_runtime.h>
#include <cuda_bf16.h>
#include <cstdint>
#include <cstddef>

// Problem constants
#define BB 4
#define LL 4096
#define DD 1024
#define HH 16
#define HDIM 64
#define KSEL 1024
#define ATT_SCALE 0.125f   // 1/sqrt(64)

typedef unsigned int uint32;

// ---------------------------------------------------------------------------
// Device scratch (static __device__ arrays: allocation-free per harness rules)
// ---------------------------------------------------------------------------
__device__ float g_scores[BB * LL];
__device__ int   g_idx[BB * KSEL];
__device__ float g_qb[(size_t)BB * KSEL * DD];
__device__ float g_kb[(size_t)BB * KSEL * DD];
__device__ float g_vb[(size_t)BB * KSEL * DD];
__device__ float g_ob[(size_t)BB * KSEL * DD];
__device__ float g_wT[(size_t)4 * DD * DD];   // transposed weights [N][K]

// ---------------------------------------------------------------------------
// Helpers (only non-arch-specific PTX: ldmatrix / mma.sync / cvt — sm_80 ISA)
// ---------------------------------------------------------------------------
__device__ __forceinline__ uint32 smem_u32(const void* p) {
    uint32 a;
    asm("{ .reg .u64 t; cvta.to.shared.u64 t, %1; cvt.u32.u64 %0, t; }"
        : "=r"(a) : "l"(p));
    return a;
}
// pack two fp32 -> bf16x2 (second arg -> bits[0:16), first -> bits[16:32))
__device__ __forceinline__ uint32 bfpack(float hi, float lo) {
    uint32 r;
    asm("cvt.rn.bf16x2.f32 %0, %1, %2;" : "=r"(r) : "f"(hi), "f"(lo));
    return r;
}
__device__ __forceinline__ void ldmat4(uint32* r, uint32 addr) {
    asm volatile("ldmatrix.sync.aligned.m8n8.x4.shared.b16 {%0,%1,%2,%3}, [%4];"
                 : "=r"(r[0]), "=r"(r[1]), "=r"(r[2]), "=r"(r[3]) : "r"(addr));
}
__device__ __forceinline__ void mma16816(float* c, const uint32* a,
                                         uint32 b0, uint32 b1) {
    asm volatile(
        "mma.sync.aligned.m16n8k16.row.col.f32.bf16.bf16.f32 "
        "{%0,%1,%2,%3}, {%4,%5,%6,%7}, {%8,%9}, {%0,%1,%2,%3};"
        : "+f"(c[0]), "+f"(c[1]), "+f"(c[2]), "+f"(c[3])
        : "r"(a[0]), "r"(a[1]), "r"(a[2]), "r"(a[3]), "r"(b0), "r"(b1));
}
// split 8 floats into bf16 hi/lo packed words
__device__ __forceinline__ void cvt8(float4 v0, float4 v1, uint4& hi, uint4& lo) {
    float f[8] = {v0.x, v0.y, v0.z, v0.w, v1.x, v1.y, v1.z, v1.w};
    float h[8], l[8];
#pragma unroll
    for (int i = 0; i < 8; i++) {
        __nv_bfloat16 b = __float2bfloat16_rn(f[i]);
        h[i] = __bfloat162float(b);
        l[i] = f[i] - h[i];
    }
    hi.x = bfpack(h[1], h[0]); hi.y = bfpack(h[3], h[2]);
    hi.z = bfpack(h[5], h[4]); hi.w = bfpack(h[7], h[6]);
    lo.x = bfpack(l[1], l[0]); lo.y = bfpack(l[3], l[2]);
    lo.z = bfpack(l[5], l[4]); lo.w = bfpack(l[7], l[6]);
}

// ---------------------------------------------------------------------------
// 1) Router: scores[b][l] = dot(x[b,l,:], w_router)   (bias is rank-invariant)
// ---------------------------------------------------------------------------
__global__ void __launch_bounds__(256) router_kernel(const float* __restrict__ x,
                                                     const float* __restrict__ w)
{
    int warp = (blockIdx.x * blockDim.x + threadIdx.x) >> 5;
    int lane = threadIdx.x & 31;
    if (warp >= BB * LL) return;
    const float4* xr = (const float4*)(x + (size_t)warp * DD);
    const float4* wr = (const float4*)w;
    float s = 0.f;
#pragma unroll
    for (int i = lane; i < DD / 4; i += 32) {
        float4 a = xr[i], b = wr[i];
        s += a.x * b.x + a.y * b.y + a.z * b.z + a.w * b.w;
    }
#pragma unroll
    for (int o = 16; o; o >>= 1) s += __shfl_xor_sync(0xffffffffu, s, o);
    if (lane == 0) g_scores[warp] = s;
}

// ---------------------------------------------------------------------------
// 2) Top-K via full bitonic sort of 4096 (score desc, index asc) per batch.
// ---------------------------------------------------------------------------
__global__ void __launch_bounds__(1024) topk_kernel()
{
    __shared__ unsigned long long key[LL];
    const int b = blockIdx.x;
    const int tid = threadIdx.x;

    for (int i = tid; i < LL; i += 1024) {
        unsigned u = __float_as_uint(g_scores[b * LL + i]);
        u = (u & 0x80000000u) ? ~u : (u | 0x80000000u);
        unsigned inv = ~u;
        key[i] = ((unsigned long long)inv << 32) | (unsigned)i;
    }
    __syncthreads();

    for (int k = 2; k <= LL; k <<= 1) {
        for (int j = k >> 1; j > 0; j >>= 1) {
            for (int t = tid; t < LL; t += 1024) {
                int ixj = t ^ j;
                if (ixj > t) {
                    unsigned long long a = key[t], c = key[ixj];
                    bool up = ((t & k) == 0);
                    if ((a > c) == up) { key[t] = c; key[ixj] = a; }
                }
            }
            __syncthreads();
        }
    }
    if (tid < KSEL)
        g_idx[b * KSEL + tid] = (int)(key[tid] & 0xFFFFFFFFu);
}

// ---------------------------------------------------------------------------
// 2b) Weight transpose: g_wT[z][n][k] = W_z[k][n]  (z: 0=wq,1=wk,2=wv,3=wo)
// ---------------------------------------------------------------------------
__global__ void __launch_bounds__(256) transpose_kernel(const float* __restrict__ wq,
                                                        const float* __restrict__ wk,
                                                        const float* __restrict__ wv,
                                                        const float* __restrict__ wo)
{
    __shared__ float t[32][33];
    const int z = blockIdx.z;
    const float* src = (z == 0) ? wq : (z == 1) ? wk : (z == 2) ? wv : wo;
    float* dst = g_wT + (size_t)z * DD * DD;
    const int x0 = blockIdx.x * 32, y0 = blockIdx.y * 32;
    const int tx = threadIdx.x & 31, ty = threadIdx.x >> 5; // 32 x 8
#pragma unroll
    for (int dy = 0; dy < 32; dy += 8)
        t[ty + dy][tx] = src[(size_t)(y0 + ty + dy) * DD + x0 + tx];
    __syncthreads();
#pragma unroll
    for (int dy = 0; dy < 32; dy += 8)
        dst[(size_t)(x0 + ty + dy) * DD + y0 + tx] = t[tx][ty + dy];
}

// ---------------------------------------------------------------------------
// mma.sync bf16-split GEMM: C[128x128 tile] = A[M,K] @ W[K,N]
// (B given K-major as wT[N][K]). 512 threads, 16 warps 4x4, warp tile 32x32.
// K-chunks of 32, double-buffered smem, LDG prefetch overlaps MMAs.
// fp32 = bf16hi + bf16lo; D += Ahi*Bhi + Ahi*Blo + Alo*Bhi (fp32 accum).
// ---------------------------------------------------------------------------
#define GSTRIDE 80                   // smem bytes per row (64B data + 16B pad)
#define ARR_B (128 * GSTRIDE)        // 10240 bytes per tile array
#define STG_B (4 * ARR_B)            // Ahi, Alo, Bhi, Blo
#define GEMM_SMEM (2 * STG_B)        // 81920 bytes

__device__ __forceinline__ void tc_gemm_tile(const float* __restrict__ A,
                                             const int*   __restrict__ a_rows,
                                             const float* __restrict__ BT,
                                             float*       __restrict__ C,
                                             const int*   __restrict__ c_rows)
{
    extern __shared__ char smx[];
    const uint32 sb = smem_u32(smx);

    const int tid  = threadIdx.x;
    const int lane = tid & 31;
    const int wid  = tid >> 5;
    const int m0 = blockIdx.y * 128;
    const int n0 = blockIdx.x * 128;
    const int wm = (wid >> 2) * 32;    // warp row offset in tile
    const int wn = (wid & 3) * 32;     // warp col offset in tile

    // Loader coords: 4 threads per row, each 8 floats
    const int lrow = tid >> 2;          // 0..127
    const int lks  = (tid & 3) * 8;     // float offset in chunk
    int am = m0 + lrow;
    if (a_rows) am = a_rows[am];
    const float4* arow = (const float4*)(A + (size_t)am * DD + lks);
    const float4* brow = (const float4*)(BT + (size_t)(n0 + lrow) * DD + lks);
    const uint32 rowoff = (uint32)lrow * GSTRIDE + lks * 2;  // byte off in array

    // ldmatrix lane addressing: r = lane%16 (matrix row), c8 = lane/16 (k half)
    const int lr = lane & 15, lc = lane >> 4;
    const uint32 aoff = (uint32)(wm + lr) * GSTRIDE + lc * 16;
    const uint32 boff = (uint32)(wn + lr) * GSTRIDE + lc * 16;

    float acc[2][4][4];
#pragma unroll
    for (int i = 0; i < 2; i++)
#pragma unroll
        for (int j = 0; j < 4; j++)
#pragma unroll
            for (int r = 0; r < 4; r++) acc[i][j][r] = 0.f;

    // Prefetch chunk 0
    float4 pa0 = arow[0], pa1 = arow[1];
    float4 pb0 = brow[0], pb1 = brow[1];

    for (int ch = 0; ch < 32; ch++) {
        // Convert current regs, store to stage buffer
        uint4 ahi, alo, bhi, blo;
        cvt8(pa0, pa1, ahi, alo);
        cvt8(pb0, pb1, bhi, blo);
        char* stg = smx + (ch & 1) * STG_B;
        *(uint4*)(stg + 0 * ARR_B + rowoff) = ahi;
        *(uint4*)(stg + 1 * ARR_B + rowoff) = alo;
        *(uint4*)(stg + 2 * ARR_B + rowoff) = bhi;
        *(uint4*)(stg + 3 * ARR_B + rowoff) = blo;
        __syncthreads();

        // Prefetch next chunk (latency hides under MMAs below)
        if (ch < 31) {
            const float4* an = arow + (ch + 1) * 8;
            const float4* bn = brow + (ch + 1) * 8;
            pa0 = an[0]; pa1 = an[1];
            pb0 = bn[0]; pb1 = bn[1];
        }

        const uint32 stb = sb + (ch & 1) * STG_B;
#pragma unroll
        for (int kk = 0; kk < 2; kk++) {
            const uint32 kb = kk * 32;
            uint32 ah[2][4], bh[2][4], bl[2][4], al[2][4];
            ldmat4(ah[0], stb + 0 * ARR_B + aoff + kb);
            ldmat4(ah[1], stb + 0 * ARR_B + aoff + 16 * GSTRIDE + kb);
            ldmat4(bh[0], stb + 2 * ARR_B + boff + kb);
            ldmat4(bh[1], stb + 2 * ARR_B + boff + 16 * GSTRIDE + kb);
            // B fragment pairing: {b0,b1} = (k-low, k-high) of the SAME 8
            // columns -> regs [j&1] and [(j&1)+2] of the x4 result.
#pragma unroll
            for (int i = 0; i < 2; i++)
#pragma unroll
                for (int j = 0; j < 4; j++)
                    mma16816(acc[i][j], ah[i],
                             bh[j >> 1][j & 1], bh[j >> 1][(j & 1) + 2]);
            ldmat4(bl[0], stb + 3 * ARR_B + boff + kb);
            ldmat4(bl[1], stb + 3 * ARR_B + boff + 16 * GSTRIDE + kb);
#pragma unroll
            for (int i = 0; i < 2; i++)
#pragma unroll
                for (int j = 0; j < 4; j++)
                    mma16816(acc[i][j], ah[i],
                             bl[j >> 1][j & 1], bl[j >> 1][(j & 1) + 2]);
            ldmat4(al[0], stb + 1 * ARR_B + aoff + kb);
            ldmat4(al[1], stb + 1 * ARR_B + aoff + 16 * GSTRIDE + kb);
#pragma unroll
            for (int i = 0; i < 2; i++)
#pragma unroll
                for (int j = 0; j < 4; j++)
                    mma16816(acc[i][j], al[i],
                             bh[j >> 1][j & 1], bh[j >> 1][(j & 1) + 2]);
        }
    }

    // Epilogue: thread holds rows {r0, r0+8} per m-frag, col pair per n-frag
    const int r0 = lane >> 2;
    const int cc = (lane & 3) * 2;
#pragma unroll
    for (int i = 0; i < 2; i++) {
#pragma unroll
        for (int rr = 0; rr < 2; rr++) {
            int row = m0 + wm + i * 16 + r0 + rr * 8;
            int crow = c_rows ? c_rows[row] : row;
            float* cp = C + (size_t)crow * DD + n0 + wn + cc;
#pragma unroll
            for (int j = 0; j < 4; j++)
                *(float2*)(cp + j * 8) =
                    make_float2(acc[i][j][rr * 2], acc[i][j][rr * 2 + 1]);
        }
    }
}

// 3) QKV: grid (8,8,12): b = z/3, w = z%3. A rows gathered by idx.
__global__ void __launch_bounds__(512) qkv_kernel(const float* __restrict__ x)
{
    const int z = blockIdx.z;
    const int b = z / 3, w = z % 3;
    const float* BT = g_wT + (size_t)w * DD * DD;
    float* C = ((w == 0) ? g_qb : (w == 1) ? g_kb : g_vb) + (size_t)b * KSEL * DD;
    tc_gemm_tile(x + (size_t)b * LL * DD, g_idx + b * KSEL, BT, C, nullptr);
}

// 5) O projection + scatter into out[b, idx[r], :]
__global__ void __launch_bounds__(512) oproj_kernel(float* __restrict__ out)
{
    const int b = blockIdx.z;
    tc_gemm_tile(g_ob + (size_t)b * KSEL * DD, nullptr,
                 g_wT + (size_t)3 * DD * DD,
                 out + (size_t)b * LL * DD, g_idx + b * KSEL);
}

// ---------------------------------------------------------------------------
// 4) Flash-style causal attention (R3 scalar version): 64x64 tiles.
// ---------------------------------------------------------------------------
#define ATT_SMEM_FLOATS (4096 * 3 + 64 * 68)
#define ATT_SMEM_BYTES  (ATT_SMEM_FLOATS * 4)

__global__ void __launch_bounds__(256) attn_kernel()
{
    extern __shared__ float sm[];
    float* Qt = sm;           // [d][r]  64x64
    float* Kt = sm + 4096;    // [d][j]  64x64
    float* Vs = sm + 8192;    // [j][c]  64x64
    float* Ps = sm + 12288;   // [r][68] padded

    const int qt  = (int)gridDim.x - 1 - (int)blockIdx.x; // long blocks first
    const int h   = blockIdx.y;
    const int b   = blockIdx.z;
    const int tid = threadIdx.x;
    const int ty  = tid >> 4;
    const int tx  = tid & 15;
    const int q0  = qt * 64;

    const float* qbase = g_qb + (size_t)b * KSEL * DD + h * HDIM;
    const float* kbase = g_kb + (size_t)b * KSEL * DD + h * HDIM;
    const float* vbase = g_vb + (size_t)b * KSEL * DD + h * HDIM;
    float*       obase = g_ob + (size_t)b * KSEL * DD + h * HDIM;

    {
        const int r  = tid >> 2;
        const int dc = (tid & 3) << 4;
        const float* src = qbase + (size_t)(q0 + r) * DD + dc;
#pragma unroll
        for (int qd = 0; qd < 4; qd++) {
            float4 v = *(const float4*)(src + qd * 4);
            int d = dc + qd * 4;
            Qt[(d + 0) * 64 + r] = v.x * ATT_SCALE;
            Qt[(d + 1) * 64 + r] = v.y * ATT_SCALE;
            Qt[(d + 2) * 64 + r] = v.z * ATT_SCALE;
            Qt[(d + 3) * 64 + r] = v.w * ATT_SCALE;
        }
    }

    float mrow[4], lrow[4], o[4][4];
#pragma unroll
    for (int i = 0; i < 4; i++) {
        mrow[i] = -1e30f; lrow[i] = 0.f;
#pragma unroll
        for (int j = 0; j < 4; j++) o[i][j] = 0.f;
    }

    for (int kt = 0; kt <= qt; kt++) {
        __syncthreads();
        {
            const int r  = tid >> 2;
            const int dc = (tid & 3) << 4;
            const float* ks = kbase + (size_t)(kt * 64 + r) * DD + dc;
            const float* vs = vbase + (size_t)(kt * 64 + r) * DD + dc;
#pragma unroll
            for (int qd = 0; qd < 4; qd++) {
                int d = dc + qd * 4;
                float4 kv = *(const float4*)(ks + qd * 4);
                Kt[(d + 0) * 64 + r] = kv.x;
                Kt[(d + 1) * 64 + r] = kv.y;
                Kt[(d + 2) * 64 + r] = kv.z;
                Kt[(d + 3) * 64 + r] = kv.w;
                float4 vv = *(const float4*)(vs + qd * 4);
                *(float4*)&Vs[r * 64 + d] = vv;
            }
        }
        __syncthreads();

        float s[4][4];
#pragma unroll
        for (int i = 0; i < 4; i++)
#pragma unroll
            for (int j = 0; j < 4; j++) s[i][j] = 0.f;

#pragma unroll 16
        for (int d = 0; d < 64; d++) {
            float4 qa = *(const float4*)&Qt[d * 64 + ty * 4];
            float4 ka = *(const float4*)&Kt[d * 64 + tx * 4];
            s[0][0] = fmaf(qa.x, ka.x, s[0][0]); s[0][1] = fmaf(qa.x, ka.y, s[0][1]);
            s[0][2] = fmaf(qa.x, ka.z, s[0][2]); s[0][3] = fmaf(qa.x, ka.w, s[0][3]);
            s[1][0] = fmaf(qa.y, ka.x, s[1][0]); s[1][1] = fmaf(qa.y, ka.y, s[1][1]);
            s[1][2] = fmaf(qa.y, ka.z, s[1][2]); s[1][3] = fmaf(qa.y, ka.w, s[1][3]);
            s[2][0] = fmaf(qa.z, ka.x, s[2][0]); s[2][1] = fmaf(qa.z, ka.y, s[2][1]);
            s[2][2] = fmaf(qa.z, ka.z, s[2][2]); s[2][3] = fmaf(qa.z, ka.w, s[2][3]);
            s[3][0] = fmaf(qa.w, ka.x, s[3][0]); s[3][1] = fmaf(qa.w, ka.y, s[3][1]);
            s[3][2] = fmaf(qa.w, ka.z, s[3][2]); s[3][3] = fmaf(qa.w, ka.w, s[3][3]);
        }

        if (kt == qt) {
#pragma unroll
            for (int i = 0; i < 4; i++)
#pragma unroll
                for (int j = 0; j < 4; j++)
                    if (tx * 4 + j > ty * 4 + i) s[i][j] = -1e30f;
        }

#pragma unroll
        for (int i = 0; i < 4; i++) {
            float mx = fmaxf(fmaxf(s[i][0], s[i][1]), fmaxf(s[i][2], s[i][3]));
#pragma unroll
            for (int off = 8; off; off >>= 1)
                mx = fmaxf(mx, __shfl_xor_sync(0xffffffffu, mx, off));
            float mnew  = fmaxf(mrow[i], mx);
            float alpha = __expf(mrow[i] - mnew);
            mrow[i] = mnew;
            float ps = 0.f;
#pragma unroll
            for (int j = 0; j < 4; j++) {
                float p = __expf(s[i][j] - mnew);
                s[i][j] = p; ps += p;
            }
#pragma unroll
            for (int off = 8; off; off >>= 1)
                ps += __shfl_xor_sync(0xffffffffu, ps, off);
            lrow[i] = lrow[i] * alpha + ps;
#pragma unroll
            for (int j = 0; j < 4; j++) o[i][j] *= alpha;
            *(float4*)&Ps[(ty * 4 + i) * 68 + tx * 4] =
                make_float4(s[i][0], s[i][1], s[i][2], s[i][3]);
        }
        __syncthreads();

#pragma unroll 8
        for (int j = 0; j < 64; j++) {
            float4 vv = *(const float4*)&Vs[j * 64 + tx * 4];
#pragma unroll
            for (int i = 0; i < 4; i++) {
                float p = Ps[(ty * 4 + i) * 68 + j];
                o[i][0] = fmaf(p, vv.x, o[i][0]);
                o[i][1] = fmaf(p, vv.y, o[i][1]);
                o[i][2] = fmaf(p, vv.z, o[i][2]);
                o[i][3] = fmaf(p, vv.w, o[i][3]);
            }
        }
    }

#pragma unroll
    for (int i = 0; i < 4; i++) {
        float inv = 1.f / lrow[i];
        float* op = obase + (size_t)(q0 + ty * 4 + i) * DD + tx * 4;
        *(float4*)op = make_float4(o[i][0] * inv, o[i][1] * inv,
                                   o[i][2] * inv, o[i][3] * inv);
    }
}

// ---------------------------------------------------------------------------
// Launch: copy + transpose + router -> topk -> QKV(mma) -> attn -> Oproj(mma)
// ---------------------------------------------------------------------------
extern "C" void kernel_launch(void* const* d_in, const int* in_sizes, int n_in,
                              void* d_out, int out_size)
{
    const float* x  = (const float*)d_in[0];
    const float* wr = (const float*)d_in[1];
    // d_in[2] = b_router: constant bias, rank-invariant, unused
    const float* wq = (const float*)d_in[3];
    const float* wk = (const float*)d_in[4];
    const float* wv = (const float*)d_in[5];
    const float* wo = (const float*)d_in[6];
    float* out = (float*)d_out;

    // Passthrough for unselected tokens (selected rows overwritten by oproj)
    cudaMemcpyAsync(out, x, (size_t)BB * LL * DD * sizeof(float),
                    cudaMemcpyDeviceToDevice);

    transpose_kernel<<<dim3(32, 32, 4), 256>>>(wq, wk, wv, wo);
    router_kernel<<<(BB * LL) / 8, 256>>>(x, wr);
    topk_kernel<<<BB, 1024>>>();

    cudaFuncSetAttribute(qkv_kernel,
                         cudaFuncAttributeMaxDynamicSharedMemorySize, GEMM_SMEM);
    cudaFuncSetAttribute(oproj_kernel,
                         cudaFuncAttributeMaxDynamicSharedMemorySize, GEMM_SMEM);

    qkv_kernel<<<dim3(8, 8, 12), 512, GEMM_SMEM>>>(x);

    cudaFuncSetAttribute(attn_kernel,
                         cudaFuncAttributeMaxDynamicSharedMemorySize,
                         ATT_SMEM_BYTES);
    attn_kernel<<<dim3(16, HH, BB), 256, ATT_SMEM_BYTES>>>();

    oproj_kernel<<<dim3(8, 8, 4), 512, GEMM_SMEM>>>(out);
}

// round 8
// speedup vs baseline: 1.7099x; 1.5784x over previous
#include <cuda_runtime.h>
#include <cuda_bf16.h>
#include <cstdint>
#include <cstddef>

// Problem constants
#define BB 4
#define LL 4096
#define DD 1024
#define HH 16
#define HDIM 64
#define KSEL 1024
#define ATT_SCALE 0.125f   // 1/sqrt(64)

typedef unsigned int uint32;

// ---------------------------------------------------------------------------
// Device scratch (static __device__ arrays: allocation-free per harness rules)
// ---------------------------------------------------------------------------
__device__ float g_scores[BB * LL];
__device__ int   g_idx[BB * KSEL];
__device__ float g_qb[(size_t)BB * KSEL * DD];
__device__ float g_kb[(size_t)BB * KSEL * DD];
__device__ float g_vb[(size_t)BB * KSEL * DD];
__device__ float g_ob[(size_t)BB * KSEL * DD];
// Pre-split bf16 operands (hi + lo = fp32 to ~2^-22)
__device__ __nv_bfloat16 g_xshi[(size_t)BB * KSEL * DD];  // gathered x rows
__device__ __nv_bfloat16 g_xslo[(size_t)BB * KSEL * DD];
__device__ __nv_bfloat16 g_wThi[(size_t)4 * DD * DD];     // W^T [N][K]
__device__ __nv_bfloat16 g_wTlo[(size_t)4 * DD * DD];
__device__ __nv_bfloat16 g_obhi[(size_t)BB * KSEL * DD];  // attn output
__device__ __nv_bfloat16 g_oblo[(size_t)BB * KSEL * DD];

// ---------------------------------------------------------------------------
// Helpers (sm_80-era PTX only: ldmatrix / mma.sync / cp.async / cvt)
// ---------------------------------------------------------------------------
__device__ __forceinline__ uint32 smem_u32(const void* p) {
    uint32 a;
    asm("{ .reg .u64 t; cvta.to.shared.u64 t, %1; cvt.u32.u64 %0, t; }"
        : "=r"(a) : "l"(p));
    return a;
}
__device__ __forceinline__ uint32 bfpack(float hi, float lo) {
    uint32 r;
    asm("cvt.rn.bf16x2.f32 %0, %1, %2;" : "=r"(r) : "f"(hi), "f"(lo));
    return r;
}
__device__ __forceinline__ void ldmat4(uint32* r, uint32 addr) {
    asm volatile("ldmatrix.sync.aligned.m8n8.x4.shared.b16 {%0,%1,%2,%3}, [%4];"
                 : "=r"(r[0]), "=r"(r[1]), "=r"(r[2]), "=r"(r[3]) : "r"(addr));
}
__device__ __forceinline__ void mma16816(float* c, const uint32* a,
                                         uint32 b0, uint32 b1) {
    asm volatile(
        "mma.sync.aligned.m16n8k16.row.col.f32.bf16.bf16.f32 "
        "{%0,%1,%2,%3}, {%4,%5,%6,%7}, {%8,%9}, {%0,%1,%2,%3};"
        : "+f"(c[0]), "+f"(c[1]), "+f"(c[2]), "+f"(c[3])
        : "r"(a[0]), "r"(a[1]), "r"(a[2]), "r"(a[3]), "r"(b0), "r"(b1));
}
__device__ __forceinline__ void cp16(uint32 s, const void* g) {
    asm volatile("cp.async.cg.shared.global [%0], [%1], 16;"
                 :: "r"(s), "l"(g));
}
#define CP_COMMIT() asm volatile("cp.async.commit_group;")
#define CP_WAIT2()  asm volatile("cp.async.wait_group 2;")
// split 8 floats into bf16 hi/lo packed words (memory order: elem0 in low half)
__device__ __forceinline__ void cvt8(float4 v0, float4 v1, uint4& hi, uint4& lo) {
    float f[8] = {v0.x, v0.y, v0.z, v0.w, v1.x, v1.y, v1.z, v1.w};
    float h[8], l[8];
#pragma unroll
    for (int i = 0; i < 8; i++) {
        __nv_bfloat16 b = __float2bfloat16_rn(f[i]);
        h[i] = __bfloat162float(b);
        l[i] = f[i] - h[i];
    }
    hi.x = bfpack(h[1], h[0]); hi.y = bfpack(h[3], h[2]);
    hi.z = bfpack(h[5], h[4]); hi.w = bfpack(h[7], h[6]);
    lo.x = bfpack(l[1], l[0]); lo.y = bfpack(l[3], l[2]);
    lo.z = bfpack(l[5], l[4]); lo.w = bfpack(l[7], l[6]);
}

// ---------------------------------------------------------------------------
// 1) Router
// ---------------------------------------------------------------------------
__global__ void __launch_bounds__(256) router_kernel(const float* __restrict__ x,
                                                     const float* __restrict__ w)
{
    int warp = (blockIdx.x * blockDim.x + threadIdx.x) >> 5;
    int lane = threadIdx.x & 31;
    if (warp >= BB * LL) return;
    const float4* xr = (const float4*)(x + (size_t)warp * DD);
    const float4* wr = (const float4*)w;
    float s = 0.f;
#pragma unroll
    for (int i = lane; i < DD / 4; i += 32) {
        float4 a = xr[i], b = wr[i];
        s += a.x * b.x + a.y * b.y + a.z * b.z + a.w * b.w;
    }
#pragma unroll
    for (int o = 16; o; o >>= 1) s += __shfl_xor_sync(0xffffffffu, s, o);
    if (lane == 0) g_scores[warp] = s;
}

// ---------------------------------------------------------------------------
// 2) Top-K bitonic sort (desc score, asc index) per batch.
// ---------------------------------------------------------------------------
__global__ void __launch_bounds__(1024) topk_kernel()
{
    __shared__ unsigned long long key[LL];
    const int b = blockIdx.x;
    const int tid = threadIdx.x;

    for (int i = tid; i < LL; i += 1024) {
        unsigned u = __float_as_uint(g_scores[b * LL + i]);
        u = (u & 0x80000000u) ? ~u : (u | 0x80000000u);
        unsigned inv = ~u;
        key[i] = ((unsigned long long)inv << 32) | (unsigned)i;
    }
    __syncthreads();

    for (int k = 2; k <= LL; k <<= 1) {
        for (int j = k >> 1; j > 0; j >>= 1) {
            for (int t = tid; t < LL; t += 1024) {
                int ixj = t ^ j;
                if (ixj > t) {
                    unsigned long long a = key[t], c = key[ixj];
                    bool up = ((t & k) == 0);
                    if ((a > c) == up) { key[t] = c; key[ixj] = a; }
                }
            }
            __syncthreads();
        }
    }
    if (tid < KSEL)
        g_idx[b * KSEL + tid] = (int)(key[tid] & 0xFFFFFFFFu);
}

// ---------------------------------------------------------------------------
// 2b) Weight transpose + bf16 split: g_wThi/lo[z][n][k] = split(W_z[k][n])
// ---------------------------------------------------------------------------
__global__ void __launch_bounds__(256) convert_w_kernel(const float* __restrict__ wq,
                                                        const float* __restrict__ wk,
                                                        const float* __restrict__ wv,
                                                        const float* __restrict__ wo)
{
    __shared__ float t[32][33];
    const int z = blockIdx.z;
    const float* src = (z == 0) ? wq : (z == 1) ? wk : (z == 2) ? wv : wo;
    __nv_bfloat16* dh = g_wThi + (size_t)z * DD * DD;
    __nv_bfloat16* dl = g_wTlo + (size_t)z * DD * DD;
    const int x0 = blockIdx.x * 32, y0 = blockIdx.y * 32;
    const int tx = threadIdx.x & 31, ty = threadIdx.x >> 5; // 32 x 8
#pragma unroll
    for (int dy = 0; dy < 32; dy += 8)
        t[ty + dy][tx] = src[(size_t)(y0 + ty + dy) * DD + x0 + tx];
    __syncthreads();
#pragma unroll
    for (int dy = 0; dy < 32; dy += 8) {
        float v = t[tx][ty + dy];
        __nv_bfloat16 h = __float2bfloat16_rn(v);
        size_t o = (size_t)(x0 + ty + dy) * DD + y0 + tx;
        dh[o] = h;
        dl[o] = __float2bfloat16_rn(v - __bfloat162float(h));
    }
}

// ---------------------------------------------------------------------------
// 2c) Gather + bf16 split of selected x rows: g_xshi/lo[b*K+r] = split(x[b][idx])
// ---------------------------------------------------------------------------
__global__ void __launch_bounds__(256) convert_xs_kernel(const float* __restrict__ x)
{
    int t = blockIdx.x * 256 + threadIdx.x;        // one per 8 elements
    int row = t >> 7;                              // 0..4095
    int off = (t & 127) << 3;
    int b = row >> 10, r = row & 1023;
    const float* src = x + ((size_t)b * LL + g_idx[b * KSEL + r]) * DD + off;
    float4 v0 = *(const float4*)src;
    float4 v1 = *(const float4*)(src + 4);
    uint4 hi, lo;
    cvt8(v0, v1, hi, lo);
    *(uint4*)(g_xshi + (size_t)row * DD + off) = hi;
    *(uint4*)(g_xslo + (size_t)row * DD + off) = lo;
}

// 2d) Dense bf16 split of attention output for the O-projection.
__global__ void __launch_bounds__(256) convert_ob_kernel()
{
    int t = blockIdx.x * 256 + threadIdx.x;
    size_t off = (size_t)t << 3;
    float4 v0 = *(const float4*)(g_ob + off);
    float4 v1 = *(const float4*)(g_ob + off + 4);
    uint4 hi, lo;
    cvt8(v0, v1, hi, lo);
    *(uint4*)(g_obhi + off) = hi;
    *(uint4*)(g_oblo + off) = lo;
}

// ---------------------------------------------------------------------------
// bf16-split mma.sync GEMM v2: pre-converted inputs, cp.async 3-stage pipe.
// C[128x128] = (Ahi+Alo)[M,K] @ (Bhi+Blo)^T, 3 products, fp32 accum.
// 512 threads, 16 warps 4x4, warp tile 32x32, K-chunk 64.
// ---------------------------------------------------------------------------
#define GST 144                     // smem row stride (128B data + 16B pad)
#define ARR (128 * GST)             // 18432 B per array
#define STG (4 * ARR)               // Ahi, Alo, Bhi, Blo = 73728 B per stage
#define NSTAGE 3
#define GEMM_SMEM (NSTAGE * STG)    // 221184 B

__device__ __forceinline__ void bf_gemm(const __nv_bfloat16* __restrict__ Ahi,
                                        const __nv_bfloat16* __restrict__ Alo,
                                        const __nv_bfloat16* __restrict__ Bhi,
                                        const __nv_bfloat16* __restrict__ Blo,
                                        float* __restrict__ C,
                                        const int* __restrict__ c_rows)
{
    extern __shared__ char smx[];
    const uint32 sb = smem_u32(smx);

    const int tid  = threadIdx.x;
    const int lane = tid & 31;
    const int wid  = tid >> 5;
    const int m0 = blockIdx.y * 128;
    const int n0 = blockIdx.x * 128;
    const int wm = (wid >> 2) * 32;
    const int wn = (wid & 3) * 32;

    const char* ga0 = (const char*)(Ahi + (size_t)m0 * DD);
    const char* ga1 = (const char*)(Alo + (size_t)m0 * DD);
    const char* gb0 = (const char*)(Bhi + (size_t)n0 * DD);
    const char* gb1 = (const char*)(Blo + (size_t)n0 * DD);

    // Loader: per stage 4 arrays x 128 rows x 8 x 16B units; 8 units/thread.
    const int w0 = tid, w1 = 512 + tid;
    const int r0l = w0 >> 3, s0l = (w0 & 7) * 16;
    const int r1l = w1 >> 3, s1l = (w1 & 7) * 16;

#define ISSUE(ch, stg) do {                                                    \
    uint32 _sb = sb + (stg) * STG;                                             \
    size_t go0 = (size_t)r0l * 2048 + (ch) * 128 + s0l;                        \
    size_t go1 = (size_t)r1l * 2048 + (ch) * 128 + s1l;                        \
    uint32 so0 = r0l * GST + s0l, so1 = r1l * GST + s1l;                       \
    cp16(_sb + 0 * ARR + so0, ga0 + go0); cp16(_sb + 0 * ARR + so1, ga0 + go1);\
    cp16(_sb + 1 * ARR + so0, ga1 + go0); cp16(_sb + 1 * ARR + so1, ga1 + go1);\
    cp16(_sb + 2 * ARR + so0, gb0 + go0); cp16(_sb + 2 * ARR + so1, gb0 + go1);\
    cp16(_sb + 3 * ARR + so0, gb1 + go0); cp16(_sb + 3 * ARR + so1, gb1 + go1);\
    CP_COMMIT();                                                               \
} while (0)

    ISSUE(0, 0); ISSUE(1, 1); ISSUE(2, 2);

    const int lr = lane & 15, lc = lane >> 4;
    const uint32 aoff = (uint32)(wm + lr) * GST + lc * 16;
    const uint32 boff = (uint32)(wn + lr) * GST + lc * 16;

    float acc[2][4][4];
#pragma unroll
    for (int i = 0; i < 2; i++)
#pragma unroll
        for (int j = 0; j < 4; j++)
#pragma unroll
            for (int r = 0; r < 4; r++) acc[i][j][r] = 0.f;

    for (int ch = 0; ch < 16; ch++) {
        const int stg = ch % NSTAGE;
        CP_WAIT2();
        __syncthreads();
        const uint32 stb = sb + stg * STG;
#pragma unroll
        for (int kk = 0; kk < 4; kk++) {
            const uint32 kb = kk * 32;
            uint32 ah[2][4], al[2][4], bh[2][4], bl[2][4];
            ldmat4(ah[0], stb + 0 * ARR + aoff + kb);
            ldmat4(ah[1], stb + 0 * ARR + aoff + 16 * GST + kb);
            ldmat4(bh[0], stb + 2 * ARR + boff + kb);
            ldmat4(bh[1], stb + 2 * ARR + boff + 16 * GST + kb);
            // B pairing: {b0,b1} = (k-low, k-high) of SAME 8 cols -> [j&1],[(j&1)+2]
#pragma unroll
            for (int i = 0; i < 2; i++)
#pragma unroll
                for (int j = 0; j < 4; j++)
                    mma16816(acc[i][j], ah[i],
                             bh[j >> 1][j & 1], bh[j >> 1][(j & 1) + 2]);
            ldmat4(bl[0], stb + 3 * ARR + boff + kb);
            ldmat4(bl[1], stb + 3 * ARR + boff + 16 * GST + kb);
#pragma unroll
            for (int i = 0; i < 2; i++)
#pragma unroll
                for (int j = 0; j < 4; j++)
                    mma16816(acc[i][j], ah[i],
                             bl[j >> 1][j & 1], bl[j >> 1][(j & 1) + 2]);
            ldmat4(al[0], stb + 1 * ARR + aoff + kb);
            ldmat4(al[1], stb + 1 * ARR + aoff + 16 * GST + kb);
#pragma unroll
            for (int i = 0; i < 2; i++)
#pragma unroll
                for (int j = 0; j < 4; j++)
                    mma16816(acc[i][j], al[i],
                             bh[j >> 1][j & 1], bh[j >> 1][(j & 1) + 2]);
        }
        __syncthreads();
        if (ch + NSTAGE < 16) ISSUE(ch + NSTAGE, stg);
    }
#undef ISSUE

    // Epilogue
    const int er = lane >> 2;
    const int cc = (lane & 3) * 2;
#pragma unroll
    for (int i = 0; i < 2; i++) {
#pragma unroll
        for (int rr = 0; rr < 2; rr++) {
            int row = m0 + wm + i * 16 + er + rr * 8;
            int crow = c_rows ? c_rows[row] : row;
            float* cp = C + (size_t)crow * DD + n0 + wn + cc;
#pragma unroll
            for (int j = 0; j < 4; j++)
                *(float2*)(cp + j * 8) =
                    make_float2(acc[i][j][rr * 2], acc[i][j][rr * 2 + 1]);
        }
    }
}

// 3) QKV: grid (8,8,12): b = z/3, w = z%3. A pre-gathered.
__global__ void __launch_bounds__(512) qkv_kernel()
{
    const int z = blockIdx.z;
    const int b = z / 3, w = z % 3;
    const size_t ao = (size_t)b * KSEL * DD;
    const size_t wo = (size_t)w * DD * DD;
    float* C = ((w == 0) ? g_qb : (w == 1) ? g_kb : g_vb) + ao;
    bf_gemm(g_xshi + ao, g_xslo + ao, g_wThi + wo, g_wTlo + wo, C, nullptr);
}

// 5) O projection + scatter into out[b, idx[r], :]
__global__ void __launch_bounds__(512) oproj_kernel(float* __restrict__ out)
{
    const int b = blockIdx.z;
    const size_t ao = (size_t)b * KSEL * DD;
    const size_t wo = (size_t)3 * DD * DD;
    bf_gemm(g_obhi + ao, g_oblo + ao, g_wThi + wo, g_wTlo + wo,
            out + (size_t)b * LL * DD, g_idx + b * KSEL);
}

// ---------------------------------------------------------------------------
// 4) Flash-style causal attention (scalar, proven): 64x64 tiles.
// ---------------------------------------------------------------------------
#define ATT_SMEM_FLOATS (4096 * 3 + 64 * 68)
#define ATT_SMEM_BYTES  (ATT_SMEM_FLOATS * 4)

__global__ void __launch_bounds__(256) attn_kernel()
{
    extern __shared__ float sm[];
    float* Qt = sm;           // [d][r]  64x64
    float* Kt = sm + 4096;    // [d][j]  64x64
    float* Vs = sm + 8192;    // [j][c]  64x64
    float* Ps = sm + 12288;   // [r][68] padded

    const int qt  = (int)gridDim.x - 1 - (int)blockIdx.x;
    const int h   = blockIdx.y;
    const int b   = blockIdx.z;
    const int tid = threadIdx.x;
    const int ty  = tid >> 4;
    const int tx  = tid & 15;
    const int q0  = qt * 64;

    const float* qbase = g_qb + (size_t)b * KSEL * DD + h * HDIM;
    const float* kbase = g_kb + (size_t)b * KSEL * DD + h * HDIM;
    const float* vbase = g_vb + (size_t)b * KSEL * DD + h * HDIM;
    float*       obase = g_ob + (size_t)b * KSEL * DD + h * HDIM;

    {
        const int r  = tid >> 2;
        const int dc = (tid & 3) << 4;
        const float* src = qbase + (size_t)(q0 + r) * DD + dc;
#pragma unroll
        for (int qd = 0; qd < 4; qd++) {
            float4 v = *(const float4*)(src + qd * 4);
            int d = dc + qd * 4;
            Qt[(d + 0) * 64 + r] = v.x * ATT_SCALE;
            Qt[(d + 1) * 64 + r] = v.y * ATT_SCALE;
            Qt[(d + 2) * 64 + r] = v.z * ATT_SCALE;
            Qt[(d + 3) * 64 + r] = v.w * ATT_SCALE;
        }
    }

    float mrow[4], lrow[4], o[4][4];
#pragma unroll
    for (int i = 0; i < 4; i++) {
        mrow[i] = -1e30f; lrow[i] = 0.f;
#pragma unroll
        for (int j = 0; j < 4; j++) o[i][j] = 0.f;
    }

    for (int kt = 0; kt <= qt; kt++) {
        __syncthreads();
        {
            const int r  = tid >> 2;
            const int dc = (tid & 3) << 4;
            const float* ks = kbase + (size_t)(kt * 64 + r) * DD + dc;
            const float* vs = vbase + (size_t)(kt * 64 + r) * DD + dc;
#pragma unroll
            for (int qd = 0; qd < 4; qd++) {
                int d = dc + qd * 4;
                float4 kv = *(const float4*)(ks + qd * 4);
                Kt[(d + 0) * 64 + r] = kv.x;
                Kt[(d + 1) * 64 + r] = kv.y;
                Kt[(d + 2) * 64 + r] = kv.z;
                Kt[(d + 3) * 64 + r] = kv.w;
                float4 vv = *(const float4*)(vs + qd * 4);
                *(float4*)&Vs[r * 64 + d] = vv;
            }
        }
        __syncthreads();

        float s[4][4];
#pragma unroll
        for (int i = 0; i < 4; i++)
#pragma unroll
            for (int j = 0; j < 4; j++) s[i][j] = 0.f;

#pragma unroll 16
        for (int d = 0; d < 64; d++) {
            float4 qa = *(const float4*)&Qt[d * 64 + ty * 4];
            float4 ka = *(const float4*)&Kt[d * 64 + tx * 4];
            s[0][0] = fmaf(qa.x, ka.x, s[0][0]); s[0][1] = fmaf(qa.x, ka.y, s[0][1]);
            s[0][2] = fmaf(qa.x, ka.z, s[0][2]); s[0][3] = fmaf(qa.x, ka.w, s[0][3]);
            s[1][0] = fmaf(qa.y, ka.x, s[1][0]); s[1][1] = fmaf(qa.y, ka.y, s[1][1]);
            s[1][2] = fmaf(qa.y, ka.z, s[1][2]); s[1][3] = fmaf(qa.y, ka.w, s[1][3]);
            s[2][0] = fmaf(qa.z, ka.x, s[2][0]); s[2][1] = fmaf(qa.z, ka.y, s[2][1]);
            s[2][2] = fmaf(qa.z, ka.z, s[2][2]); s[2][3] = fmaf(qa.z, ka.w, s[2][3]);
            s[3][0] = fmaf(qa.w, ka.x, s[3][0]); s[3][1] = fmaf(qa.w, ka.y, s[3][1]);
            s[3][2] = fmaf(qa.w, ka.z, s[3][2]); s[3][3] = fmaf(qa.w, ka.w, s[3][3]);
        }

        if (kt == qt) {
#pragma unroll
            for (int i = 0; i < 4; i++)
#pragma unroll
                for (int j = 0; j < 4; j++)
                    if (tx * 4 + j > ty * 4 + i) s[i][j] = -1e30f;
        }

#pragma unroll
        for (int i = 0; i < 4; i++) {
            float mx = fmaxf(fmaxf(s[i][0], s[i][1]), fmaxf(s[i][2], s[i][3]));
#pragma unroll
            for (int off = 8; off; off >>= 1)
                mx = fmaxf(mx, __shfl_xor_sync(0xffffffffu, mx, off));
            float mnew  = fmaxf(mrow[i], mx);
            float alpha = __expf(mrow[i] - mnew);
            mrow[i] = mnew;
            float ps = 0.f;
#pragma unroll
            for (int j = 0; j < 4; j++) {
                float p = __expf(s[i][j] - mnew);
                s[i][j] = p; ps += p;
            }
#pragma unroll
            for (int off = 8; off; off >>= 1)
                ps += __shfl_xor_sync(0xffffffffu, ps, off);
            lrow[i] = lrow[i] * alpha + ps;
#pragma unroll
            for (int j = 0; j < 4; j++) o[i][j] *= alpha;
            *(float4*)&Ps[(ty * 4 + i) * 68 + tx * 4] =
                make_float4(s[i][0], s[i][1], s[i][2], s[i][3]);
        }
        __syncthreads();

#pragma unroll 8
        for (int j = 0; j < 64; j++) {
            float4 vv = *(const float4*)&Vs[j * 64 + tx * 4];
#pragma unroll
            for (int i = 0; i < 4; i++) {
                float p = Ps[(ty * 4 + i) * 68 + j];
                o[i][0] = fmaf(p, vv.x, o[i][0]);
                o[i][1] = fmaf(p, vv.y, o[i][1]);
                o[i][2] = fmaf(p, vv.z, o[i][2]);
                o[i][3] = fmaf(p, vv.w, o[i][3]);
            }
        }
    }

#pragma unroll
    for (int i = 0; i < 4; i++) {
        float inv = 1.f / lrow[i];
        float* op = obase + (size_t)(q0 + ty * 4 + i) * DD + tx * 4;
        *(float4*)op = make_float4(o[i][0] * inv, o[i][1] * inv,
                                   o[i][2] * inv, o[i][3] * inv);
    }
}

// ---------------------------------------------------------------------------
// Launch
// ---------------------------------------------------------------------------
extern "C" void kernel_launch(void* const* d_in, const int* in_sizes, int n_in,
                              void* d_out, int out_size)
{
    const float* x  = (const float*)d_in[0];
    const float* wr = (const float*)d_in[1];
    // d_in[2] = b_router: constant bias, rank-invariant, unused
    const float* wq = (const float*)d_in[3];
    const float* wk = (const float*)d_in[4];
    const float* wv = (const float*)d_in[5];
    const float* wo = (const float*)d_in[6];
    float* out = (float*)d_out;

    // Passthrough for unselected tokens (selected rows overwritten by oproj)
    cudaMemcpyAsync(out, x, (size_t)BB * LL * DD * sizeof(float),
                    cudaMemcpyDeviceToDevice);

    convert_w_kernel<<<dim3(32, 32, 4), 256>>>(wq, wk, wv, wo);
    router_kernel<<<(BB * LL) / 8, 256>>>(x, wr);
    topk_kernel<<<BB, 1024>>>();
    convert_xs_kernel<<<2048, 256>>>(x);

    cudaFuncSetAttribute(qkv_kernel,
                         cudaFuncAttributeMaxDynamicSharedMemorySize, GEMM_SMEM);
    cudaFuncSetAttribute(oproj_kernel,
                         cudaFuncAttributeMaxDynamicSharedMemorySize, GEMM_SMEM);

    qkv_kernel<<<dim3(8, 8, 12), 512, GEMM_SMEM>>>();

    cudaFuncSetAttribute(attn_kernel,
                         cudaFuncAttributeMaxDynamicSharedMemorySize,
                         ATT_SMEM_BYTES);
    attn_kernel<<<dim3(16, HH, BB), 256, ATT_SMEM_BYTES>>>();

    convert_ob_kernel<<<2048, 256>>>();
    oproj_kernel<<<dim3(8, 8, 4), 512, GEMM_SMEM>>>(out);
}

// round 9
// speedup vs baseline: 2.4795x; 1.4500x over previous
#include <cuda_runtime.h>
#include <cuda_bf16.h>
#include <cstdint>
#include <cstddef>

// Problem constants
#define BB 4
#define LL 4096
#define DD 1024
#define HH 16
#define HDIM 64
#define KSEL 1024
#define ATT_SCALE 0.125f   // 1/sqrt(64)

typedef unsigned int uint32;

// ---------------------------------------------------------------------------
// Device scratch
// ---------------------------------------------------------------------------
__device__ float g_scores[BB * LL];
__device__ int   g_idx[BB * KSEL];
// Pre-split bf16 operands (hi + lo ~= fp32 to ~2^-17 relative)
__device__ __nv_bfloat16 g_xshi[(size_t)BB * KSEL * DD];  // gathered x rows
__device__ __nv_bfloat16 g_xslo[(size_t)BB * KSEL * DD];
__device__ __nv_bfloat16 g_wThi[(size_t)4 * DD * DD];     // W^T [N][K]
__device__ __nv_bfloat16 g_wTlo[(size_t)4 * DD * DD];
__device__ __nv_bfloat16 g_qhi[(size_t)BB * KSEL * DD];   // Q pre-scaled
__device__ __nv_bfloat16 g_qlo[(size_t)BB * KSEL * DD];
__device__ __nv_bfloat16 g_khi[(size_t)BB * KSEL * DD];
__device__ __nv_bfloat16 g_klo[(size_t)BB * KSEL * DD];
__device__ __nv_bfloat16 g_vhi[(size_t)BB * KSEL * DD];
__device__ __nv_bfloat16 g_vlo[(size_t)BB * KSEL * DD];
__device__ __nv_bfloat16 g_obhi[(size_t)BB * KSEL * DD];  // attn output
__device__ __nv_bfloat16 g_oblo[(size_t)BB * KSEL * DD];

// ---------------------------------------------------------------------------
// Helpers (sm_80-era PTX only)
// ---------------------------------------------------------------------------
__device__ __forceinline__ uint32 smem_u32(const void* p) {
    uint32 a;
    asm("{ .reg .u64 t; cvta.to.shared.u64 t, %1; cvt.u32.u64 %0, t; }"
        : "=r"(a) : "l"(p));
    return a;
}
__device__ __forceinline__ uint32 bfpack(float hi, float lo) {
    uint32 r;
    asm("cvt.rn.bf16x2.f32 %0, %1, %2;" : "=r"(r) : "f"(hi), "f"(lo));
    return r;
}
__device__ __forceinline__ void ldmat4(uint32* r, uint32 addr) {
    asm volatile("ldmatrix.sync.aligned.m8n8.x4.shared.b16 {%0,%1,%2,%3}, [%4];"
                 : "=r"(r[0]), "=r"(r[1]), "=r"(r[2]), "=r"(r[3]) : "r"(addr));
}
__device__ __forceinline__ void ldmat4t(uint32* r, uint32 addr) {
    asm volatile("ldmatrix.sync.aligned.m8n8.x4.trans.shared.b16 {%0,%1,%2,%3}, [%4];"
                 : "=r"(r[0]), "=r"(r[1]), "=r"(r[2]), "=r"(r[3]) : "r"(addr));
}
__device__ __forceinline__ void mma16816(float* c, const uint32* a,
                                         uint32 b0, uint32 b1) {
    asm volatile(
        "mma.sync.aligned.m16n8k16.row.col.f32.bf16.bf16.f32 "
        "{%0,%1,%2,%3}, {%4,%5,%6,%7}, {%8,%9}, {%0,%1,%2,%3};"
        : "+f"(c[0]), "+f"(c[1]), "+f"(c[2]), "+f"(c[3])
        : "r"(a[0]), "r"(a[1]), "r"(a[2]), "r"(a[3]), "r"(b0), "r"(b1));
}
__device__ __forceinline__ void cp16(uint32 s, const void* g) {
    asm volatile("cp.async.cg.shared.global [%0], [%1], 16;" :: "r"(s), "l"(g));
}
#define CP_COMMIT()  asm volatile("cp.async.commit_group;")
#define CP_WAIT2()   asm volatile("cp.async.wait_group 2;")
#define CP_WAITALL() asm volatile("cp.async.wait_all;")
// split 8 floats into bf16 hi/lo packed words (elem0 in low half)
__device__ __forceinline__ void cvt8(float4 v0, float4 v1, uint4& hi, uint4& lo) {
    float f[8] = {v0.x, v0.y, v0.z, v0.w, v1.x, v1.y, v1.z, v1.w};
    float h[8], l[8];
#pragma unroll
    for (int i = 0; i < 8; i++) {
        __nv_bfloat16 b = __float2bfloat16_rn(f[i]);
        h[i] = __bfloat162float(b);
        l[i] = f[i] - h[i];
    }
    hi.x = bfpack(h[1], h[0]); hi.y = bfpack(h[3], h[2]);
    hi.z = bfpack(h[5], h[4]); hi.w = bfpack(h[7], h[6]);
    lo.x = bfpack(l[1], l[0]); lo.y = bfpack(l[3], l[2]);
    lo.z = bfpack(l[5], l[4]); lo.w = bfpack(l[7], l[6]);
}

// ---------------------------------------------------------------------------
// 1) Router
// ---------------------------------------------------------------------------
__global__ void __launch_bounds__(256) router_kernel(const float* __restrict__ x,
                                                     const float* __restrict__ w)
{
    int warp = (blockIdx.x * blockDim.x + threadIdx.x) >> 5;
    int lane = threadIdx.x & 31;
    if (warp >= BB * LL) return;
    const float4* xr = (const float4*)(x + (size_t)warp * DD);
    const float4* wr = (const float4*)w;
    float s = 0.f;
#pragma unroll
    for (int i = lane; i < DD / 4; i += 32) {
        float4 a = xr[i], b = wr[i];
        s += a.x * b.x + a.y * b.y + a.z * b.z + a.w * b.w;
    }
#pragma unroll
    for (int o = 16; o; o >>= 1) s += __shfl_xor_sync(0xffffffffu, s, o);
    if (lane == 0) g_scores[warp] = s;
}

// ---------------------------------------------------------------------------
// 2) Top-K bitonic sort (desc score, asc index) per batch.
// ---------------------------------------------------------------------------
__global__ void __launch_bounds__(1024) topk_kernel()
{
    __shared__ unsigned long long key[LL];
    const int b = blockIdx.x;
    const int tid = threadIdx.x;

    for (int i = tid; i < LL; i += 1024) {
        unsigned u = __float_as_uint(g_scores[b * LL + i]);
        u = (u & 0x80000000u) ? ~u : (u | 0x80000000u);
        unsigned inv = ~u;
        key[i] = ((unsigned long long)inv << 32) | (unsigned)i;
    }
    __syncthreads();

    for (int k = 2; k <= LL; k <<= 1) {
        for (int j = k >> 1; j > 0; j >>= 1) {
            for (int t = tid; t < LL; t += 1024) {
                int ixj = t ^ j;
                if (ixj > t) {
                    unsigned long long a = key[t], c = key[ixj];
                    bool up = ((t & k) == 0);
                    if ((a > c) == up) { key[t] = c; key[ixj] = a; }
                }
            }
            __syncthreads();
        }
    }
    if (tid < KSEL)
        g_idx[b * KSEL + tid] = (int)(key[tid] & 0xFFFFFFFFu);
}

// ---------------------------------------------------------------------------
// 2b) Weight transpose + bf16 split
// ---------------------------------------------------------------------------
__global__ void __launch_bounds__(256) convert_w_kernel(const float* __restrict__ wq,
                                                        const float* __restrict__ wk,
                                                        const float* __restrict__ wv,
                                                        const float* __restrict__ wo)
{
    __shared__ float t[32][33];
    const int z = blockIdx.z;
    const float* src = (z == 0) ? wq : (z == 1) ? wk : (z == 2) ? wv : wo;
    __nv_bfloat16* dh = g_wThi + (size_t)z * DD * DD;
    __nv_bfloat16* dl = g_wTlo + (size_t)z * DD * DD;
    const int x0 = blockIdx.x * 32, y0 = blockIdx.y * 32;
    const int tx = threadIdx.x & 31, ty = threadIdx.x >> 5;
#pragma unroll
    for (int dy = 0; dy < 32; dy += 8)
        t[ty + dy][tx] = src[(size_t)(y0 + ty + dy) * DD + x0 + tx];
    __syncthreads();
#pragma unroll
    for (int dy = 0; dy < 32; dy += 8) {
        float v = t[tx][ty + dy];
        __nv_bfloat16 h = __float2bfloat16_rn(v);
        size_t o = (size_t)(x0 + ty + dy) * DD + y0 + tx;
        dh[o] = h;
        dl[o] = __float2bfloat16_rn(v - __bfloat162float(h));
    }
}

// 2c) Gather + bf16 split of selected x rows
__global__ void __launch_bounds__(256) convert_xs_kernel(const float* __restrict__ x)
{
    int t = blockIdx.x * 256 + threadIdx.x;
    int row = t >> 7;
    int off = (t & 127) << 3;
    int b = row >> 10, r = row & 1023;
    const float* src = x + ((size_t)b * LL + g_idx[b * KSEL + r]) * DD + off;
    float4 v0 = *(const float4*)src;
    float4 v1 = *(const float4*)(src + 4);
    uint4 hi, lo;
    cvt8(v0, v1, hi, lo);
    *(uint4*)(g_xshi + (size_t)row * DD + off) = hi;
    *(uint4*)(g_xslo + (size_t)row * DD + off) = lo;
}

// ---------------------------------------------------------------------------
// bf16-split mma.sync GEMM (cp.async 3-stage). Epilogue: fp32+scatter, or
// bf16 hi/lo split (optionally scaled).
// ---------------------------------------------------------------------------
#define GST 144
#define ARR (128 * GST)
#define STG (4 * ARR)
#define NSTAGE 3
#define GEMM_SMEM (NSTAGE * STG)

__device__ __forceinline__ void bf_gemm(const __nv_bfloat16* __restrict__ Ahi,
                                        const __nv_bfloat16* __restrict__ Alo,
                                        const __nv_bfloat16* __restrict__ Bhi,
                                        const __nv_bfloat16* __restrict__ Blo,
                                        float* __restrict__ Cf,
                                        const int* __restrict__ c_rows,
                                        __nv_bfloat16* __restrict__ Chi,
                                        __nv_bfloat16* __restrict__ Clo,
                                        float scale)
{
    extern __shared__ char smx[];
    const uint32 sb = smem_u32(smx);

    const int tid  = threadIdx.x;
    const int lane = tid & 31;
    const int wid  = tid >> 5;
    const int m0 = blockIdx.y * 128;
    const int n0 = blockIdx.x * 128;
    const int wm = (wid >> 2) * 32;
    const int wn = (wid & 3) * 32;

    const char* ga0 = (const char*)(Ahi + (size_t)m0 * DD);
    const char* ga1 = (const char*)(Alo + (size_t)m0 * DD);
    const char* gb0 = (const char*)(Bhi + (size_t)n0 * DD);
    const char* gb1 = (const char*)(Blo + (size_t)n0 * DD);

    const int w0 = tid, w1 = 512 + tid;
    const int r0l = w0 >> 3, s0l = (w0 & 7) * 16;
    const int r1l = w1 >> 3, s1l = (w1 & 7) * 16;

#define ISSUE(ch, stg) do {                                                    \
    uint32 _sb = sb + (stg) * STG;                                             \
    size_t go0 = (size_t)r0l * 2048 + (ch) * 128 + s0l;                        \
    size_t go1 = (size_t)r1l * 2048 + (ch) * 128 + s1l;                        \
    uint32 so0 = r0l * GST + s0l, so1 = r1l * GST + s1l;                       \
    cp16(_sb + 0 * ARR + so0, ga0 + go0); cp16(_sb + 0 * ARR + so1, ga0 + go1);\
    cp16(_sb + 1 * ARR + so0, ga1 + go0); cp16(_sb + 1 * ARR + so1, ga1 + go1);\
    cp16(_sb + 2 * ARR + so0, gb0 + go0); cp16(_sb + 2 * ARR + so1, gb0 + go1);\
    cp16(_sb + 3 * ARR + so0, gb1 + go0); cp16(_sb + 3 * ARR + so1, gb1 + go1);\
    CP_COMMIT();                                                               \
} while (0)

    ISSUE(0, 0); ISSUE(1, 1); ISSUE(2, 2);

    const int lr = lane & 15, lc = lane >> 4;
    const uint32 aoff = (uint32)(wm + lr) * GST + lc * 16;
    const uint32 boff = (uint32)(wn + lr) * GST + lc * 16;

    float acc[2][4][4];
#pragma unroll
    for (int i = 0; i < 2; i++)
#pragma unroll
        for (int j = 0; j < 4; j++)
#pragma unroll
            for (int r = 0; r < 4; r++) acc[i][j][r] = 0.f;

    for (int ch = 0; ch < 16; ch++) {
        const int stg = ch % NSTAGE;
        CP_WAIT2();
        __syncthreads();
        const uint32 stb = sb + stg * STG;
#pragma unroll
        for (int kk = 0; kk < 4; kk++) {
            const uint32 kb = kk * 32;
            uint32 ah[2][4], al[2][4], bh[2][4], bl[2][4];
            ldmat4(ah[0], stb + 0 * ARR + aoff + kb);
            ldmat4(ah[1], stb + 0 * ARR + aoff + 16 * GST + kb);
            ldmat4(bh[0], stb + 2 * ARR + boff + kb);
            ldmat4(bh[1], stb + 2 * ARR + boff + 16 * GST + kb);
#pragma unroll
            for (int i = 0; i < 2; i++)
#pragma unroll
                for (int j = 0; j < 4; j++)
                    mma16816(acc[i][j], ah[i],
                             bh[j >> 1][j & 1], bh[j >> 1][(j & 1) + 2]);
            ldmat4(bl[0], stb + 3 * ARR + boff + kb);
            ldmat4(bl[1], stb + 3 * ARR + boff + 16 * GST + kb);
#pragma unroll
            for (int i = 0; i < 2; i++)
#pragma unroll
                for (int j = 0; j < 4; j++)
                    mma16816(acc[i][j], ah[i],
                             bl[j >> 1][j & 1], bl[j >> 1][(j & 1) + 2]);
            ldmat4(al[0], stb + 1 * ARR + aoff + kb);
            ldmat4(al[1], stb + 1 * ARR + aoff + 16 * GST + kb);
#pragma unroll
            for (int i = 0; i < 2; i++)
#pragma unroll
                for (int j = 0; j < 4; j++)
                    mma16816(acc[i][j], al[i],
                             bh[j >> 1][j & 1], bh[j >> 1][(j & 1) + 2]);
        }
        __syncthreads();
        if (ch + NSTAGE < 16) ISSUE(ch + NSTAGE, stg);
    }
#undef ISSUE

    const int er = lane >> 2;
    const int cc = (lane & 3) * 2;
#pragma unroll
    for (int i = 0; i < 2; i++) {
#pragma unroll
        for (int rr = 0; rr < 2; rr++) {
            int row = m0 + wm + i * 16 + er + rr * 8;
            if (Cf) {
                int crow = c_rows ? c_rows[row] : row;
                float* cp = Cf + (size_t)crow * DD + n0 + wn + cc;
#pragma unroll
                for (int j = 0; j < 4; j++)
                    *(float2*)(cp + j * 8) =
                        make_float2(acc[i][j][rr * 2], acc[i][j][rr * 2 + 1]);
            } else {
                size_t base = (size_t)row * DD + n0 + wn + cc;
#pragma unroll
                for (int j = 0; j < 4; j++) {
                    float v0 = acc[i][j][rr * 2] * scale;
                    float v1 = acc[i][j][rr * 2 + 1] * scale;
                    float h0 = __bfloat162float(__float2bfloat16_rn(v0));
                    float h1 = __bfloat162float(__float2bfloat16_rn(v1));
                    *(uint32*)(Chi + base + j * 8) = bfpack(h1, h0);
                    *(uint32*)(Clo + base + j * 8) = bfpack(v1 - h1, v0 - h0);
                }
            }
        }
    }
}

// 3) QKV: grid (8,8,12): b = z/3, w = z%3. Outputs bf16 hi/lo (Q pre-scaled).
__global__ void __launch_bounds__(512) qkv_kernel()
{
    const int z = blockIdx.z;
    const int b = z / 3, w = z % 3;
    const size_t ao = (size_t)b * KSEL * DD;
    const size_t wo = (size_t)w * DD * DD;
    __nv_bfloat16* Chi = ((w == 0) ? g_qhi : (w == 1) ? g_khi : g_vhi) + ao;
    __nv_bfloat16* Clo = ((w == 0) ? g_qlo : (w == 1) ? g_klo : g_vlo) + ao;
    bf_gemm(g_xshi + ao, g_xslo + ao, g_wThi + wo, g_wTlo + wo,
            nullptr, nullptr, Chi, Clo, (w == 0) ? ATT_SCALE : 1.0f);
}

// 5) O projection + scatter into out[b, idx[r], :]
__global__ void __launch_bounds__(512) oproj_kernel(float* __restrict__ out)
{
    const int b = blockIdx.z;
    const size_t ao = (size_t)b * KSEL * DD;
    const size_t wo = (size_t)3 * DD * DD;
    bf_gemm(g_obhi + ao, g_oblo + ao, g_wThi + wo, g_wTlo + wo,
            out + (size_t)b * LL * DD, g_idx + b * KSEL, nullptr, nullptr, 1.0f);
}

// ---------------------------------------------------------------------------
// 4) Tensor-core flash attention: 64 q-rows/block, 4 warps x 16 rows.
//    S = Qhi*Khi + Qhi*Klo + Qlo*Khi ; PV = Phi*Vhi + Phi*Vlo + Plo*Vhi.
// ---------------------------------------------------------------------------
#define AGST 144
#define AARR (64 * AGST)           // 9216 B per 64x64 bf16 array

__global__ void __launch_bounds__(128) attn_kernel()
{
    __shared__ char asmem[4 * AARR];   // slots: Khi, Klo, Vhi, Vlo (Q staged first)
    const uint32 sb = smem_u32(asmem);

    const int qt  = (int)gridDim.x - 1 - (int)blockIdx.x; // long blocks first
    const int h   = blockIdx.y;
    const int b   = blockIdx.z;
    const int tid = threadIdx.x;
    const int lane = tid & 31;
    const int wid  = tid >> 5;     // 0..3, warp owns rows wid*16..+15
    const int q0  = qt * 64;

    const size_t bh = (size_t)b * KSEL * DD + h * HDIM;
    const __nv_bfloat16* pqh = g_qhi + bh;
    const __nv_bfloat16* pql = g_qlo + bh;
    const __nv_bfloat16* pkh = g_khi + bh;
    const __nv_bfloat16* pkl = g_klo + bh;
    const __nv_bfloat16* pvh = g_vhi + bh;
    const __nv_bfloat16* pvl = g_vlo + bh;

    // ---- Stage Q tile (hi->slot0, lo->slot1), grab A-fragments to registers
#pragma unroll
    for (int i = 0; i < 8; i++) {
        int u = (i & 3) * 128 + tid;         // 0..511
        int a = i >> 2;                      // 0=hi, 1=lo
        int r = u >> 3, c = u & 7;
        const __nv_bfloat16* src = (a ? pql : pqh) + (size_t)(q0 + r) * DD + c * 8;
        cp16(sb + a * AARR + r * AGST + c * 16, src);
    }
    CP_COMMIT(); CP_WAITALL();
    __syncthreads();

    const int lr = lane & 15, lc = lane >> 4;
    uint32 qh[4][4], ql[4][4];
    {
        uint32 qbase = sb + (uint32)(wid * 16 + lr) * AGST + lc * 16;
#pragma unroll
        for (int t = 0; t < 4; t++) {
            ldmat4(qh[t], qbase + t * 32);
            ldmat4(ql[t], qbase + AARR + t * 32);
        }
    }
    __syncthreads();   // Q fragments in regs; slots can be overwritten

    float oacc[8][4];
#pragma unroll
    for (int nb = 0; nb < 8; nb++)
#pragma unroll
        for (int r = 0; r < 4; r++) oacc[nb][r] = 0.f;
    float mrow[2] = {-1e30f, -1e30f};
    float lrow[2] = {0.f, 0.f};

    const int rbase = lane >> 2;         // row within 8 (c0,c1); +8 for c2,c3
    const int cbase = (lane & 3) * 2;

    for (int kt = 0; kt <= qt; kt++) {
        // ---- load K/V tiles (Khi, Klo, Vhi, Vlo)
#pragma unroll
        for (int i = 0; i < 16; i++) {
            int u = (i & 3) * 128 + tid;
            int a = i >> 2;
            int r = u >> 3, c = u & 7;
            const __nv_bfloat16* base =
                (a == 0) ? pkh : (a == 1) ? pkl : (a == 2) ? pvh : pvl;
            cp16(sb + a * AARR + r * AGST + c * 16,
                 base + (size_t)(kt * 64 + r) * DD + c * 8);
        }
        CP_COMMIT(); CP_WAITALL();
        __syncthreads();

        // ---- S = Q K^T (3 products)
        float s[8][4];
#pragma unroll
        for (int nb = 0; nb < 8; nb++)
#pragma unroll
            for (int r = 0; r < 4; r++) s[nb][r] = 0.f;

#pragma unroll
        for (int t = 0; t < 4; t++) {
            uint32 kb = sb + (uint32)lr * AGST + lc * 16 + t * 32;
            uint32 bh_[4][4], bl_[4][4];
#pragma unroll
            for (int jp = 0; jp < 4; jp++) {
                ldmat4(bh_[jp], kb + jp * 16 * AGST);
                ldmat4(bl_[jp], kb + AARR + jp * 16 * AGST);
            }
#pragma unroll
            for (int nb = 0; nb < 8; nb++) {
                int jp = nb >> 1, e = nb & 1;
                mma16816(s[nb], qh[t], bh_[jp][e], bh_[jp][e + 2]);
                mma16816(s[nb], qh[t], bl_[jp][e], bl_[jp][e + 2]);
                mma16816(s[nb], ql[t], bh_[jp][e], bh_[jp][e + 2]);
            }
        }

        // ---- causal mask on diagonal tile (local row/col compare)
        if (kt == qt) {
#pragma unroll
            for (int nb = 0; nb < 8; nb++) {
#pragma unroll
                for (int r = 0; r < 4; r++) {
                    int rloc = wid * 16 + rbase + (r >> 1) * 8;
                    int cloc = nb * 8 + cbase + (r & 1);
                    if (cloc > rloc) s[nb][r] = -1e30f;
                }
            }
        }

        // ---- online softmax (rows: half 0 -> c0,c1 ; half 1 -> c2,c3)
#pragma unroll
        for (int half = 0; half < 2; half++) {
            float mx = -1e30f;
#pragma unroll
            for (int nb = 0; nb < 8; nb++)
                mx = fmaxf(mx, fmaxf(s[nb][half * 2], s[nb][half * 2 + 1]));
            mx = fmaxf(mx, __shfl_xor_sync(0xffffffffu, mx, 1));
            mx = fmaxf(mx, __shfl_xor_sync(0xffffffffu, mx, 2));
            float mnew = fmaxf(mrow[half], mx);
            float al = __expf(mrow[half] - mnew);
            mrow[half] = mnew;
            float ps = 0.f;
#pragma unroll
            for (int nb = 0; nb < 8; nb++) {
                float p0 = __expf(s[nb][half * 2] - mnew);
                float p1 = __expf(s[nb][half * 2 + 1] - mnew);
                s[nb][half * 2] = p0; s[nb][half * 2 + 1] = p1;
                ps += p0 + p1;
            }
            ps += __shfl_xor_sync(0xffffffffu, ps, 1);
            ps += __shfl_xor_sync(0xffffffffu, ps, 2);
            lrow[half] = lrow[half] * al + ps;
#pragma unroll
            for (int nb = 0; nb < 8; nb++) {
                oacc[nb][half * 2]     *= al;
                oacc[nb][half * 2 + 1] *= al;
            }
        }

        // ---- O += P V (P split in regs; V^T fragments via ldmatrix.trans)
#pragma unroll
        for (int t = 0; t < 4; t++) {
            uint32 ah[4], al_[4];
#pragma unroll
            for (int f = 0; f < 4; f++) {
                // f: 0 -> (row r, k-low) = s[2t][0,1]; 1 -> (r+8, k-low) = s[2t][2,3]
                //    2 -> (r, k-high) = s[2t+1][0,1]; 3 -> (r+8,k-high) = s[2t+1][2,3]
                int nb = 2 * t + (f >> 1);
                float p0 = s[nb][(f & 1) * 2];
                float p1 = s[nb][(f & 1) * 2 + 1];
                float h0 = __bfloat162float(__float2bfloat16_rn(p0));
                float h1 = __bfloat162float(__float2bfloat16_rn(p1));
                ah[f]  = bfpack(h1, h0);
                al_[f] = bfpack(p1 - h1, p0 - h0);
            }
            uint32 vb = sb + 2 * AARR + (uint32)(t * 16 + lr) * AGST + lc * 16;
            uint32 vh_[4][4], vl_[4][4];
#pragma unroll
            for (int dp = 0; dp < 4; dp++) {
                ldmat4t(vh_[dp], vb + dp * 32);
                ldmat4t(vl_[dp], vb + AARR + dp * 32);
            }
#pragma unroll
            for (int nb = 0; nb < 8; nb++) {
                int dp = nb >> 1, e = (nb & 1) * 2;
                mma16816(oacc[nb], ah,  vh_[dp][e], vh_[dp][e + 1]);
                mma16816(oacc[nb], ah,  vl_[dp][e], vl_[dp][e + 1]);
                mma16816(oacc[nb], al_, vh_[dp][e], vh_[dp][e + 1]);
            }
        }
        __syncthreads();   // done reading tiles; next kt may overwrite
    }

    // ---- epilogue: normalize, split to bf16 hi/lo, store
#pragma unroll
    for (int half = 0; half < 2; half++) {
        float inv = 1.f / lrow[half];
        int grow = q0 + wid * 16 + rbase + half * 8;
        size_t base = (size_t)((size_t)b * KSEL + grow) * DD + h * HDIM;
#pragma unroll
        for (int nb = 0; nb < 8; nb++) {
            float v0 = oacc[nb][half * 2] * inv;
            float v1 = oacc[nb][half * 2 + 1] * inv;
            float h0 = __bfloat162float(__float2bfloat16_rn(v0));
            float h1 = __bfloat162float(__float2bfloat16_rn(v1));
            size_t o = base + nb * 8 + cbase;
            *(uint32*)(g_obhi + o) = bfpack(h1, h0);
            *(uint32*)(g_oblo + o) = bfpack(v1 - h1, v0 - h0);
        }
    }
}

// ---------------------------------------------------------------------------
// Launch
// ---------------------------------------------------------------------------
extern "C" void kernel_launch(void* const* d_in, const int* in_sizes, int n_in,
                              void* d_out, int out_size)
{
    const float* x  = (const float*)d_in[0];
    const float* wr = (const float*)d_in[1];
    // d_in[2] = b_router: constant bias, rank-invariant, unused
    const float* wq = (const float*)d_in[3];
    const float* wk = (const float*)d_in[4];
    const float* wv = (const float*)d_in[5];
    const float* wo = (const float*)d_in[6];
    float* out = (float*)d_out;

    // Passthrough for unselected tokens (selected rows overwritten by oproj)
    cudaMemcpyAsync(out, x, (size_t)BB * LL * DD * sizeof(float),
                    cudaMemcpyDeviceToDevice);

    convert_w_kernel<<<dim3(32, 32, 4), 256>>>(wq, wk, wv, wo);
    router_kernel<<<(BB * LL) / 8, 256>>>(x, wr);
    topk_kernel<<<BB, 1024>>>();
    convert_xs_kernel<<<2048, 256>>>(x);

    cudaFuncSetAttribute(qkv_kernel,
                         cudaFuncAttributeMaxDynamicSharedMemorySize, GEMM_SMEM);
    cudaFuncSetAttribute(oproj_kernel,
                         cudaFuncAttributeMaxDynamicSharedMemorySize, GEMM_SMEM);

    qkv_kernel<<<dim3(8, 8, 12), 512, GEMM_SMEM>>>();

    attn_kernel<<<dim3(16, HH, BB), 128>>>();

    oproj_kernel<<<dim3(8, 8, 4), 512, GEMM_SMEM>>>(out);
}